// round 2
// baseline (speedup 1.0000x reference)
#include <cuda_runtime.h>
#include <cstdint>

// Max-unpooling 2x2 stride 2, (32,64,112,112) -> (32,64,224,224).
// Non-overlapping windows => pure gather/expand, no atomics, no zero pass.
// Each thread: 4 consecutive input pixels (float4 + int4 load),
// writes 8 output floats on each of 2 rows (4x STG.128).

static constexpr int H_IN  = 112;
static constexpr int W_IN  = 112;
static constexpr int W_OUT = 224;
static constexpr int HW_IN = H_IN * W_IN;       // 12544
static constexpr int HW_OUT = W_OUT * W_OUT;    // 50176

__global__ void __launch_bounds__(256) unpool_kernel(
    const float* __restrict__ fm,
    const int*   __restrict__ sw,
    float*       __restrict__ out,
    int total4)
{
    int t = blockIdx.x * blockDim.x + threadIdx.x;
    if (t >= total4) return;

    int idx = t * 4;                 // first input pixel index
    int bc  = idx / HW_IN;
    int rem = idx - bc * HW_IN;
    int h   = rem / W_IN;
    int w   = rem - h * W_IN;        // multiple of 4

    float4 v = reinterpret_cast<const float4*>(fm)[t];
    int4   s = reinterpret_cast<const int4*>(sw)[t];

    // input pixel j (value vj, switch sj) maps to:
    //   top row (2h):     col 2(w+j) + sj      if sj < 2
    //   bottom row (2h+1):col 2(w+j) + sj - 2  if sj >= 2
    float4 top0, top1, bot0, bot1;
    top0.x = (s.x == 0) ? v.x : 0.0f;
    top0.y = (s.x == 1) ? v.x : 0.0f;
    top0.z = (s.y == 0) ? v.y : 0.0f;
    top0.w = (s.y == 1) ? v.y : 0.0f;
    top1.x = (s.z == 0) ? v.z : 0.0f;
    top1.y = (s.z == 1) ? v.z : 0.0f;
    top1.z = (s.w == 0) ? v.w : 0.0f;
    top1.w = (s.w == 1) ? v.w : 0.0f;

    bot0.x = (s.x == 2) ? v.x : 0.0f;
    bot0.y = (s.x == 3) ? v.x : 0.0f;
    bot0.z = (s.y == 2) ? v.y : 0.0f;
    bot0.w = (s.y == 3) ? v.y : 0.0f;
    bot1.x = (s.z == 2) ? v.z : 0.0f;
    bot1.y = (s.z == 3) ? v.z : 0.0f;
    bot1.z = (s.w == 2) ? v.w : 0.0f;
    bot1.w = (s.w == 3) ? v.w : 0.0f;

    size_t obase = (size_t)bc * HW_OUT + (size_t)(2 * h) * W_OUT + 2 * w;
    float4* orow0 = reinterpret_cast<float4*>(out + obase);
    float4* orow1 = reinterpret_cast<float4*>(out + obase + W_OUT);
    orow0[0] = top0;
    orow0[1] = top1;
    orow1[0] = bot0;
    orow1[1] = bot1;
}

extern "C" void kernel_launch(void* const* d_in, const int* in_sizes, int n_in,
                              void* d_out, int out_size)
{
    const float* fm = (const float*)d_in[0];
    const int*   sw = (const int*)d_in[1];
    float*       out = (float*)d_out;

    int total  = in_sizes[0];            // 32*64*112*112 = 25690112
    int total4 = (total + 3) / 4;        // 6422528 (exactly divisible here)
    int threads = 256;
    int blocks  = (total4 + threads - 1) / threads;  // 25088
    unpool_kernel<<<blocks, threads>>>(fm, sw, out, total4);
}